// round 5
// baseline (speedup 1.0000x reference)
#include <cuda_runtime.h>
#include <cstdint>

// Problem constants
#define BATCH 32
#define TT 512
#define NINP 128
#define NHID 1024
#define KTOT (NINP + NHID)        // 1152
#define DT_C 0.042f
#define EPSH 512.0f               // HARMONIC = N_HID * 0.5

// Geometry: 128 CTAs = 32 col-groups x 4 batch-groups, 512 threads (16 warps)
#define NCTA 128
#define COLS 32
#define BPC  8
#define TPB  512
#define NW   16
#define KSL  (KTOT / NW)          // 72 k-rows per warp

#define BTH (BATCH * TT * NHID)

// SMEM (floats): w_s [1152][32] k-major, in_s [1152][8], red [16][256]
#define OFF_W   0
#define SZ_W    (KTOT * COLS)                 // 36864
#define OFF_IN  (OFF_W + SZ_W)
#define SZ_IN   (KTOT * BPC)                  // 9216
#define OFF_RED (OFF_IN + SZ_IN)
#define SZ_RED  (NW * COLS * BPC)             // 4096
#define SMEM_FLOATS (OFF_RED + SZ_RED)
#define SMEM_BYTES  (SMEM_FLOATS * 4)         // 200704 B

// ---- device scratch ----
__device__ float g_xT2[4 * TT * NINP * BPC];   // [bg][t][i][8b]
__device__ float g_hyT2[2][4][NHID * BPC];     // [parity][bg][h][8b]
__device__ volatile unsigned g_flagsB[4][32];  // [bg][cgrp]

typedef unsigned long long ull;

__device__ __forceinline__ void ffma2(ull& acc, ull a, ull b) {
    asm("fma.rn.f32x2 %0, %1, %2, %0;" : "+l"(acc) : "l"(a), "l"(b));
}
__device__ __forceinline__ ull add2(ull a, ull b) {
    ull r; asm("add.rn.f32x2 %0, %1, %2;" : "=l"(r) : "l"(a), "l"(b)); return r;
}
__device__ __forceinline__ ull pack2(float lo, float hi) {
    ull r; asm("mov.b64 %0, {%1, %2};" : "=l"(r) : "f"(lo), "f"(hi)); return r;
}

// ------------------------------------------------------------------
__global__ void k_init() {
    int idx = blockIdx.x * blockDim.x + threadIdx.x;
    if (idx < NCTA) ((volatile unsigned*)g_flagsB)[idx] = 0;
    int stride = gridDim.x * blockDim.x;
    for (int i = idx; i < 4 * NHID * BPC; i += stride)
        g_hyT2[0][0][i] = 0.0f;   // zero parity-0 (all 4 bgs contiguous)
}

__global__ void k_zero(float* __restrict__ p, int n4) {
    int idx = blockIdx.x * blockDim.x + threadIdx.x;
    int stride = gridDim.x * blockDim.x;
    float4 z = make_float4(0.f, 0.f, 0.f, 0.f);
    float4* p4 = reinterpret_cast<float4*>(p);
    for (int i = idx; i < n4; i += stride) p4[i] = z;
}

// x[b][t][i] -> g_xT2[bg][t][i][b&7]
__global__ void k_xpose(const float* __restrict__ x) {
    int idx = blockIdx.x * blockDim.x + threadIdx.x;
    int stride = gridDim.x * blockDim.x;
    const int N = 4 * TT * NINP * BPC;
    for (int o = idx; o < N; o += stride) {
        int blo = o & 7;
        int i = (o >> 3) & (NINP - 1);
        int t = (o >> 10) & (TT - 1);
        int bg = o >> 19;
        g_xT2[o] = x[((size_t)(bg * 8 + blo) * TT + t) * NINP + i];
    }
}

// ------------------------------------------------------------------
// persistent recurrent kernel
// GEMM lane mapping: lane = kr*8 + cq (kr=lane>>3 in 0..3, cq=lane&7 in 0..7)
//   inner step: 4 k-rows x 32 cols; weight LDS.128 contiguous, hy broadcast.
// ------------------------------------------------------------------
__global__ void __launch_bounds__(TPB, 1) k_recur(
    const float* __restrict__ x2h,
    const float* __restrict__ h2h,
    const float* __restrict__ gamma,
    const float* __restrict__ eps,
    const float* __restrict__ bias,
    float* __restrict__ out)
{
    extern __shared__ float sm[];
    float* w_s  = sm + OFF_W;     // [KTOT][32] k-major
    float* in_s = sm + OFF_IN;    // [KTOT][8]
    float* red  = sm + OFF_RED;   // [NW][32 cols][8 b]

    const int tid  = threadIdx.x;
    const int wid  = tid >> 5;
    const int lane = tid & 31;
    const int kr   = lane >> 3;   // 0..3
    const int cq   = lane & 7;    // 0..7
    const int cgrp = blockIdx.x >> 2;
    const int bg   = blockIdx.x & 3;
    const int cg0  = cgrp * COLS;
    const int b0g  = bg * BPC;
    const int kb   = wid * KSL;

    // --- weights into SMEM, k-major stride 32 (coalesced both sides) ---
    for (int idx = tid; idx < KTOT * COLS; idx += TPB) {
        int k = idx >> 5;
        int c = idx & 31;
        w_s[idx] = (k < NINP) ? x2h[(size_t)k * NHID + cg0 + c]
                              : h2h[(size_t)(k - NINP) * NHID + cg0 + c];
    }

    // --- update-phase params (tid<256: c=tid>>3, b=tid&7) ---
    float hy_r = 0.f, hz_r = 0.f;
    float gam = 0.f, epc = 0.f, bi = 0.f;
    if (tid < 256) {
        int hg = cg0 + (tid >> 3);
        gam = gamma[hg];
        epc = eps[hg] * EPSH;
        bi  = bias[hg];
    }

    // --- this warp's producer flag range (hy rows [kb,kb+72) - 128) ---
    int p0 = 0, nprod = 0;
    {
        int ke = kb + KSL;
        if (ke > NINP) {
            int hr0 = (kb > NINP ? kb : NINP) - NINP;
            int hr1 = ke - NINP;               // exclusive
            p0 = hr0 >> 5;
            nprod = ((hr1 - 1) >> 5) - p0 + 1; // <= 4
        }
    }

    const float4* xs_all = (const float4*)(g_xT2 + (size_t)bg * (TT * NINP * BPC));
    const float4* wql = (const float4*)w_s + lane;

    __syncthreads();

    for (int t = 0; t < TT; t++) {
        const int p = t & 1;

        // ---- fine-grained poll: only this warp's producers ----
        if (lane < nprod) {
            const unsigned want = (unsigned)t;
            while (g_flagsB[bg][p0 + lane] < want) { }
            __threadfence();   // acquire
        }
        __syncwarp();

        // ---- stage own 72 rows: 144 float4 (x via L1, hy via L2) ----
        {
            const float4* xs = xs_all + (size_t)t * (NINP * BPC / 4);
            const float4* hs = (const float4*)(&g_hyT2[p][bg][0]);
            float4* dst = (float4*)(in_s + kb * BPC);
            const int base2 = kb * 2;
#pragma unroll
            for (int i = lane; i < KSL * 2; i += 32) {
                int f4 = base2 + i;
                float4 v = (f4 < NINP * 2) ? __ldg(&xs[f4]) : __ldcg(&hs[f4 - NINP * 2]);
                dst[i] = v;
            }
        }
        __syncwarp();

        // ---- GEMM: 18 chunks x (4 k-rows, 32 cols, 8 batches) ----
        ull A[16];
#pragma unroll
        for (int i = 0; i < 16; i++) A[i] = 0ull;

#pragma unroll
        for (int ch = 0; ch < KSL / 4; ch++) {
            const int k0 = kb + ch * 4;
            float4 wv = wql[k0 * 8];                         // contiguous 512B/warp
            const ulonglong2* hp = (const ulonglong2*)(in_s + (k0 + kr) * BPC);
            ulonglong2 ha = hp[0];                            // batches 0..3
            ulonglong2 hb = hp[1];                            // batches 4..7
            ull w2;
            w2 = pack2(wv.x, wv.x);
            ffma2(A[0], w2, ha.x);  ffma2(A[1], w2, ha.y);
            ffma2(A[2], w2, hb.x);  ffma2(A[3], w2, hb.y);
            w2 = pack2(wv.y, wv.y);
            ffma2(A[4], w2, ha.x);  ffma2(A[5], w2, ha.y);
            ffma2(A[6], w2, hb.x);  ffma2(A[7], w2, hb.y);
            w2 = pack2(wv.z, wv.z);
            ffma2(A[8], w2, ha.x);  ffma2(A[9], w2, ha.y);
            ffma2(A[10], w2, hb.x); ffma2(A[11], w2, hb.y);
            w2 = pack2(wv.w, wv.w);
            ffma2(A[12], w2, ha.x); ffma2(A[13], w2, ha.y);
            ffma2(A[14], w2, hb.x); ffma2(A[15], w2, hb.y);
        }

        // ---- butterfly over kr (lane bits 4 then 3): lane ends with one col ----
        {
            const bool up1 = (lane & 16) != 0;
#pragma unroll
            for (int i = 0; i < 8; i++) {
                ull mine  = up1 ? A[i + 8] : A[i];
                ull other = up1 ? A[i]     : A[i + 8];
                A[i] = add2(mine, __shfl_xor_sync(0xffffffffu, other, 16));
            }
            const bool up2 = (lane & 8) != 0;
#pragma unroll
            for (int i = 0; i < 4; i++) {
                ull mine  = up2 ? A[i + 4] : A[i];
                ull other = up2 ? A[i]     : A[i + 4];
                A[i] = add2(mine, __shfl_xor_sync(0xffffffffu, other, 8));
            }
        }

        // ---- store partials: red[wid][col][8b], col = 4*cq + kr ----
        {
            const int col = 4 * cq + kr;
            ulonglong2* rp = (ulonglong2*)(red + wid * (COLS * BPC) + col * BPC);
            rp[0] = make_ulonglong2(A[0], A[1]);
            rp[1] = make_ulonglong2(A[2], A[3]);
        }
        __syncthreads();

        // ---- update: tid<256, c=tid>>3, b=tid&7 (coalesced red + hy store) ----
        if (tid < 256) {
            float pre = bi;
#pragma unroll
            for (int w = 0; w < NW; w++)
                pre += red[w * (COLS * BPC) + tid];
            float drive = tanhf(pre);
            hz_r += DT_C * (drive - gam * hy_r - epc * hz_r);
            hy_r += DT_C * hz_r;

            const int c = tid >> 3, b = tid & 7;
            const size_t obase = (size_t)(b0g + b) * (TT * NHID) + (size_t)t * NHID + cg0 + c;
            out[obase]       = hy_r;
            out[obase + BTH] = hz_r;
            __stcg(&g_hyT2[p ^ 1][bg][cg0 * BPC + tid], hy_r);   // coalesced 1KB
        }
        __syncthreads();

        // ---- release flag ----
        if (tid == 0) {
            __threadfence();
            g_flagsB[bg][cgrp] = (unsigned)(t + 1);
        }
    }
}

// ------------------------------------------------------------------
extern "C" void kernel_launch(void* const* d_in, const int* in_sizes, int n_in,
                              void* d_out, int out_size) {
    const float* x     = (const float*)d_in[0];
    const float* x2h   = (const float*)d_in[1];
    const float* h2h   = (const float*)d_in[2];
    const float* gamma = (const float*)d_in[3];
    const float* eps   = (const float*)d_in[4];
    const float* bias  = (const float*)d_in[5];
    float* out = (float*)d_out;

    static bool attr_set = false;
    if (!attr_set) {
        cudaFuncSetAttribute(k_recur, cudaFuncAttributeMaxDynamicSharedMemorySize, SMEM_BYTES);
        attr_set = true;
    }

    k_init<<<64, 256>>>();
    k_xpose<<<512, 256>>>(x);
    // u and spike outputs are identically zero (u never leaves 0)
    k_zero<<<2048, 256>>>(out + (size_t)2 * BTH, (2 * BTH) / 4);
    k_recur<<<NCTA, TPB, SMEM_BYTES>>>(x2h, h2h, gamma, eps, bias, out);
}

// round 6
// speedup vs baseline: 1.1694x; 1.1694x over previous
#include <cuda_runtime.h>
#include <cstdint>

// Problem constants
#define BATCH 32
#define TT 512
#define NINP 128
#define NHID 1024
#define KTOT (NINP + NHID)        // 1152
#define DT_C 0.042f
#define EPSH 512.0f               // HARMONIC = N_HID * 0.5

// Geometry: 128 CTAs = 32 col-groups x 4 batch-groups, 256 threads (8 warps)
#define NCTA 128
#define COLS 32
#define BPC  8
#define TPB  256
#define NW   8
#define KSL  (KTOT / NW)          // 144 k-rows per warp

#define BTH (BATCH * TT * NHID)

// SMEM (floats)
#define OFF_W   0
#define SZ_W    (KTOT * COLS)                 // 36864  (packed [k/4][32][4])
#define OFF_IN  (OFF_W + SZ_W)
#define SZ_IN   (KTOT * BPC)                  // 9216   ([k][8b], warp-private rows)
#define OFF_RED (OFF_IN + SZ_IN)
#define SZ_RED  (NW * COLS * BPC)             // 2048   ([w][col][b])
#define SMEM_FLOATS (OFF_RED + SZ_RED)
#define SMEM_BYTES  (SMEM_FLOATS * 4)         // 192512 B

// ---- device scratch ----
__device__ float g_xT2[4 * TT * NINP * BPC];   // [bg][t][i][8b]
__device__ float g_hyT2[2][4][NHID * BPC];     // [parity][bg][h][8b]
__device__ __align__(128) unsigned g_flags[4][32];  // [bg][cgrp], one 128B line per bg

typedef unsigned long long ull;

__device__ __forceinline__ void ffma2(ull& acc, ull a, ull b) {
    asm("fma.rn.f32x2 %0, %1, %2, %0;" : "+l"(acc) : "l"(a), "l"(b));
}
__device__ __forceinline__ ull pack2(float lo, float hi) {
    ull r; asm("mov.b64 %0, {%1, %2};" : "=l"(r) : "f"(lo), "f"(hi)); return r;
}
__device__ __forceinline__ void unpack2(ull v, float& lo, float& hi) {
    asm("mov.b64 {%0, %1}, %2;" : "=f"(lo), "=f"(hi) : "l"(v));
}
__device__ __forceinline__ unsigned ld_acq(const unsigned* p) {
    unsigned v;
    asm volatile("ld.global.acquire.gpu.u32 %0, [%1];" : "=r"(v) : "l"(p));
    return v;
}
__device__ __forceinline__ void st_rel(unsigned* p, unsigned v) {
    asm volatile("st.global.release.gpu.u32 [%0], %1;" :: "l"(p), "r"(v));
}

// ------------------------------------------------------------------
__global__ void k_init() {
    int idx = blockIdx.x * blockDim.x + threadIdx.x;
    if (idx < NCTA) (&g_flags[0][0])[idx] = 0;
    int stride = gridDim.x * blockDim.x;
    for (int i = idx; i < 4 * NHID * BPC; i += stride)
        g_hyT2[0][0][i] = 0.0f;
}

__global__ void k_zero(float* __restrict__ p, int n4) {
    int idx = blockIdx.x * blockDim.x + threadIdx.x;
    int stride = gridDim.x * blockDim.x;
    float4 z = make_float4(0.f, 0.f, 0.f, 0.f);
    float4* p4 = reinterpret_cast<float4*>(p);
    for (int i = idx; i < n4; i += stride) p4[i] = z;
}

// x[b][t][i] -> g_xT2[bg][t][i][b&7]
__global__ void k_xpose(const float* __restrict__ x) {
    int idx = blockIdx.x * blockDim.x + threadIdx.x;
    int stride = gridDim.x * blockDim.x;
    const int N = 4 * TT * NINP * BPC;
    for (int o = idx; o < N; o += stride) {
        int blo = o & 7;
        int i = (o >> 3) & (NINP - 1);
        int t = (o >> 10) & (TT - 1);
        int bg = o >> 19;
        g_xT2[o] = x[((size_t)(bg * 8 + blo) * TT + t) * NINP + i];
    }
}

// ------------------------------------------------------------------
// persistent recurrent kernel: 128 CTAs x 256 threads
// GEMM: lane = col; weights packed so LDS.128 per 4 k-rows is dense &
// conflict-free; hy rows read as 16B broadcasts (crossbar floor).
// ------------------------------------------------------------------
__global__ void __launch_bounds__(TPB, 1) k_recur(
    const float* __restrict__ x2h,
    const float* __restrict__ h2h,
    const float* __restrict__ gamma,
    const float* __restrict__ eps,
    const float* __restrict__ bias,
    float* __restrict__ out)
{
    extern __shared__ float sm[];
    float* w_s  = sm + OFF_W;     // packed [k/4][32][4]
    float* in_s = sm + OFF_IN;    // [k][8]
    float* red  = sm + OFF_RED;   // [w][col][8b]

    const int tid  = threadIdx.x;
    const int wid  = tid >> 5;
    const int lane = tid & 31;
    const int cgrp = blockIdx.x >> 2;
    const int bg   = blockIdx.x & 3;
    const int cg0  = cgrp * COLS;
    const int b0g  = bg * BPC;
    const int kb   = wid * KSL;

    // --- weights: global coalesced read -> packed SMEM ---
    for (int idx = tid; idx < KTOT * COLS; idx += TPB) {
        int k = idx >> 5;
        int c = idx & 31;
        float v = (k < NINP) ? x2h[(size_t)k * NHID + cg0 + c]
                             : h2h[(size_t)(k - NINP) * NHID + cg0 + c];
        w_s[((k >> 2) << 7) + (c << 2) + (k & 3)] = v;
    }

    // --- update-phase params (all 256 threads: c=tid&31, b=tid>>5) ---
    const int uc = tid & 31;
    const int ub = tid >> 5;
    const int hg = cg0 + uc;
    float hy_r = 0.f, hz_r = 0.f;
    const float gam = gamma[hg];
    const float epc = eps[hg] * EPSH;
    const float bi  = bias[hg];

    // --- this warp's producer flags (hy rows [kb,kb+144) - 128) ---
    int p0 = 0, nprod = 0;
    {
        int ke = kb + KSL;
        if (ke > NINP) {
            int h0 = ((kb > NINP) ? kb : NINP) - NINP;
            int h1 = ke - NINP - 1;
            p0 = h0 >> 5;
            nprod = (h1 >> 5) - p0 + 1;   // <= 5
        }
    }
    const unsigned* myflags = &g_flags[bg][p0];

    const float4* xs_all = (const float4*)(g_xT2 + (size_t)bg * (TT * NINP * BPC));
    const float4* wp4 = (const float4*)w_s + ((kb >> 2) << 5) + lane;
    float4* dst4 = (float4*)(in_s + kb * BPC);
    const int f4base = kb * 2;

    __syncthreads();

    for (int t = 0; t < TT; t++) {
        const int p = t & 1;

        // ---- poll own producers: flag >= t means hy(t) is visible ----
        if (lane < nprod) {
            const unsigned want = (unsigned)t;
            while (ld_acq(&myflags[lane]) < want) { }
        }
        __syncwarp();

        // ---- stage own 144 rows (288 float4): x rows via L1, hy via L2 ----
        {
            const float4* xs = xs_all + (size_t)t * (NINP * BPC / 4);
            const float4* hs = (const float4*)(&g_hyT2[p][bg][0]);
#pragma unroll
            for (int i = lane; i < KSL * 2; i += 32) {
                int f4 = f4base + i;
                float4 v = (f4 < NINP * 2) ? __ldg(&xs[f4])
                                           : __ldcg(&hs[f4 - NINP * 2]);
                dst4[i] = v;
            }
        }
        __syncwarp();

        // ---- GEMM: 36 chunks x (4 k, 32 cols, 8 batches); 8 acc regs-pairs ----
        ull A0 = 0, A1 = 0, A2 = 0, A3 = 0;
#pragma unroll 4
        for (int ch = 0; ch < KSL / 4; ch++) {
            float4 wv = wp4[ch << 5];                       // dense 512B, 4 wf
            const ulonglong2* hr = (const ulonglong2*)(in_s + (kb + (ch << 2)) * BPC);
            {
                ulonglong2 ha = hr[0], hb = hr[1];
                ull w2 = pack2(wv.x, wv.x);
                ffma2(A0, w2, ha.x); ffma2(A1, w2, ha.y);
                ffma2(A2, w2, hb.x); ffma2(A3, w2, hb.y);
            }
            {
                ulonglong2 ha = hr[2], hb = hr[3];
                ull w2 = pack2(wv.y, wv.y);
                ffma2(A0, w2, ha.x); ffma2(A1, w2, ha.y);
                ffma2(A2, w2, hb.x); ffma2(A3, w2, hb.y);
            }
            {
                ulonglong2 ha = hr[4], hb = hr[5];
                ull w2 = pack2(wv.z, wv.z);
                ffma2(A0, w2, ha.x); ffma2(A1, w2, ha.y);
                ffma2(A2, w2, hb.x); ffma2(A3, w2, hb.y);
            }
            {
                ulonglong2 ha = hr[6], hb = hr[7];
                ull w2 = pack2(wv.w, wv.w);
                ffma2(A0, w2, ha.x); ffma2(A1, w2, ha.y);
                ffma2(A2, w2, hb.x); ffma2(A3, w2, hb.y);
            }
        }

        // ---- store partials: red[wid][col=lane][8b] ----
        {
            ulonglong2* rp = (ulonglong2*)(red + wid * (COLS * BPC) + lane * BPC);
            rp[0] = make_ulonglong2(A0, A1);
            rp[1] = make_ulonglong2(A2, A3);
        }
        __syncthreads();

        // ---- update: all 256 threads, c=tid&31 (coalesced out), b=tid>>5 ----
        float pre = bi;
#pragma unroll
        for (int w = 0; w < NW; w++)
            pre += red[w * (COLS * BPC) + uc * BPC + ub];
        float drive = tanhf(pre);
        hz_r += DT_C * (drive - gam * hy_r - epc * hz_r);
        hy_r += DT_C * hz_r;

        // hy state first (inter-CTA critical path), fence, flag
        __stcg(&g_hyT2[p ^ 1][bg][hg * BPC + ub], hy_r);
        __threadfence();
        __syncthreads();
        if (tid == 0) st_rel(&g_flags[bg][cgrp], (unsigned)(t + 1));

        // out stores off the critical path
        const size_t obase = (size_t)(b0g + ub) * (TT * NHID) + (size_t)t * NHID + hg;
        out[obase]       = hy_r;
        out[obase + BTH] = hz_r;
    }
}

// ------------------------------------------------------------------
extern "C" void kernel_launch(void* const* d_in, const int* in_sizes, int n_in,
                              void* d_out, int out_size) {
    const float* x     = (const float*)d_in[0];
    const float* x2h   = (const float*)d_in[1];
    const float* h2h   = (const float*)d_in[2];
    const float* gamma = (const float*)d_in[3];
    const float* eps   = (const float*)d_in[4];
    const float* bias  = (const float*)d_in[5];
    float* out = (float*)d_out;

    cudaFuncSetAttribute(k_recur, cudaFuncAttributeMaxDynamicSharedMemorySize, SMEM_BYTES);

    k_init<<<64, 256>>>();
    k_xpose<<<512, 256>>>(x);
    // u and spike outputs are identically zero (u never leaves 0)
    k_zero<<<2048, 256>>>(out + (size_t)2 * BTH, (2 * BTH) / 4);
    k_recur<<<NCTA, TPB, SMEM_BYTES>>>(x2h, h2h, gamma, eps, bias, out);
}

// round 9
// speedup vs baseline: 1.3269x; 1.1347x over previous
#include <cuda_runtime.h>
#include <cstdint>

// Problem constants
#define BATCH 32
#define TT 512
#define NINP 128
#define NHID 1024
#define KTOT 1152
#define DT_C 0.042f
#define EPSH 512.0f               // HARMONIC = N_HID * 0.5

// Geometry: 128 CTAs = 32 col-groups x 4 batch-groups, 512 threads (16 warps)
#define NCTA 128
#define COLS 32
#define BPC  8
#define TPB  512
#define NW   16
#define KSL  72                   // k-rows per warp

#define BTH (BATCH * TT * NHID)

// SMEM (floats)
#define OFF_W   0
#define SZ_W    (KTOT * COLS)     // 36864, packed [k/4][c/2][8]
#define OFF_IN  (OFF_W + SZ_W)
#define SZ_IN   (KTOT * BPC)      // 9216, [k][8b]
#define OFF_RED (OFF_IN + SZ_IN)
#define SZ_RED  (NW * COLS * BPC) // 4096, [w][(c&1)*128 + (c>>1)*8 + b]
#define SMEM_FLOATS (OFF_RED + SZ_RED)
#define SMEM_BYTES  (SMEM_FLOATS * 4)   // 200704 B

// ---- device scratch ----
__device__ float g_xT2[4 * TT * NINP * BPC];   // [bg][t][i][8b]
__device__ float g_hyT2[2][4][NHID * BPC];     // [parity][bg][h][8b]
__device__ __align__(128) unsigned g_flags[4][32];  // [bg][cgrp]

typedef unsigned long long ull;

__device__ __forceinline__ void ffma2(ull& acc, ull a, ull b) {
    asm("fma.rn.f32x2 %0, %1, %2, %0;" : "+l"(acc) : "l"(a), "l"(b));
}
__device__ __forceinline__ ull pack2(float lo, float hi) {
    ull r; asm("mov.b64 %0, {%1, %2};" : "=l"(r) : "f"(lo), "f"(hi)); return r;
}
__device__ __forceinline__ unsigned ld_acq(const unsigned* p) {
    unsigned v;
    asm volatile("ld.global.acquire.gpu.u32 %0, [%1];" : "=r"(v) : "l"(p));
    return v;
}
__device__ __forceinline__ void st_rel(unsigned* p, unsigned v) {
    asm volatile("st.global.release.gpu.u32 [%0], %1;" :: "l"(p), "r"(v));
}

// ------------------------------------------------------------------
__global__ void k_init() {
    int idx = blockIdx.x * blockDim.x + threadIdx.x;
    if (idx < NCTA) (&g_flags[0][0])[idx] = 0;
    int stride = gridDim.x * blockDim.x;
    for (int i = idx; i < 4 * NHID * BPC; i += stride)
        g_hyT2[0][0][i] = 0.0f;
}

__global__ void k_zero(float* __restrict__ p, int n4) {
    int idx = blockIdx.x * blockDim.x + threadIdx.x;
    int stride = gridDim.x * blockDim.x;
    float4 z = make_float4(0.f, 0.f, 0.f, 0.f);
    float4* p4 = reinterpret_cast<float4*>(p);
    for (int i = idx; i < n4; i += stride) p4[i] = z;
}

// x[b][t][i] -> g_xT2[bg][t][i][b&7]
__global__ void k_xpose(const float* __restrict__ x) {
    int idx = blockIdx.x * blockDim.x + threadIdx.x;
    int stride = gridDim.x * blockDim.x;
    const int N = 4 * TT * NINP * BPC;
    for (int o = idx; o < N; o += stride) {
        int blo = o & 7;
        int i = (o >> 3) & (NINP - 1);
        int t = (o >> 10) & (TT - 1);
        int bg = o >> 19;
        g_xT2[o] = x[((size_t)(bg * 8 + blo) * TT + t) * NINP + i];
    }
}

// ------------------------------------------------------------------
// persistent recurrent kernel: 128 CTAs x 512 threads
// GEMM lane = 2*cp + h: cp = col-pair (0..15), h = batch-half (0..1).
//   weights: dense packed LDS.128 (byte floor)
//   hy rows: one 16B load/row, 2 distinct addrs/warp -> 1 wf/row
// ------------------------------------------------------------------
__global__ void __launch_bounds__(TPB, 1) k_recur(
    const float* __restrict__ x2h,
    const float* __restrict__ h2h,
    const float* __restrict__ gamma,
    const float* __restrict__ eps,
    const float* __restrict__ bias,
    float* __restrict__ out)
{
    extern __shared__ float sm[];
    float* w_s  = sm + OFF_W;     // packed [kq][cp][r0c0,r0c1,r1c0,r1c1,r2c0,r2c1,r3c0,r3c1]
    float* in_s = sm + OFF_IN;    // [k][8b]
    float* red  = sm + OFF_RED;   // [w][256]

    const int tid  = threadIdx.x;
    const int wid  = tid >> 5;
    const int lane = tid & 31;
    const int cp   = lane >> 1;   // 0..15
    const int h    = lane & 1;    // 0..1
    const int cgrp = blockIdx.x >> 2;
    const int bg   = blockIdx.x & 3;
    const int cg0  = cgrp * COLS;
    const int b0g  = bg * BPC;
    const int kb   = wid * KSL;

    // --- weights: coalesced global read -> packed SMEM ---
    for (int idx = tid; idx < KTOT * COLS; idx += TPB) {
        int k = idx >> 5;
        int c = idx & 31;
        float v = (k < NINP) ? x2h[(size_t)k * NHID + cg0 + c]
                             : h2h[(size_t)(k - NINP) * NHID + cg0 + c];
        w_s[((k >> 2) << 7) + ((c >> 1) << 3) + ((k & 3) << 1) + (c & 1)] = v;
    }

    // --- update params (tid<256: uc=tid&31, ub=tid>>5) ---
    const int uc = tid & 31;
    const int ub = (tid >> 5) & 7;
    const int hg = cg0 + uc;
    float hy_r = 0.f, hz_r = 0.f;
    float gam = 0.f, epc = 0.f, bi = 0.f;
    if (tid < 256) {
        gam = gamma[hg];
        epc = eps[hg] * EPSH;
        bi  = bias[hg];
    }

    // --- producer flags for this warp's hy rows [kb-128, kb+72-128) ---
    int p0 = 0, npf = 0;
    {
        int ke = kb + KSL;
        if (ke > NINP) {
            int h0 = ((kb > NINP) ? kb : NINP) - NINP;
            int h1 = ke - NINP - 1;
            p0 = h0 >> 5;
            npf = (h1 >> 5) - p0 + 1;   // <= 4
        }
    }
    const unsigned* myf = &g_flags[bg][p0];

    const float4* xs_all = (const float4*)(g_xT2 + (size_t)bg * (TT * NINP * BPC));
    const float4* wq = (const float4*)w_s + ((kb >> 2) << 5) + (cp << 1);
    float4* dst4 = (float4*)in_s;
    float* rw = red + wid * (COLS * BPC);

    __syncthreads();

    for (int t = 0; t < TT; t++) {
        const int p = t & 1;

        // ---- poll own producers (flag >= t -> hy(p) visible) ----
        if (lane < npf) {
            const unsigned want = (unsigned)t;
            while (ld_acq(myf + lane) < want) { }
        }
        __syncwarp();

        // ---- stage own 72 rows (144 float4): x via L1, hy via L2 ----
        {
            const float4* xs = xs_all + (size_t)t * (NINP * BPC / 4);
            const float4* hy4 = (const float4*)(&g_hyT2[p][bg][0]);
#pragma unroll
            for (int i = lane; i < KSL * 2; i += 32) {
                int f4 = kb * 2 + i;
                float4 v = (f4 < NINP * 2) ? __ldg(xs + f4)
                                           : __ldcg(hy4 + (f4 - NINP * 2));
                dst4[f4] = v;
            }
        }
        __syncwarp();

        // ---- GEMM: 18 chunks x (4 k-rows, 2 cols/lane, 4 batches/lane) ----
        ull A00 = 0, A01 = 0, A10 = 0, A11 = 0;
        const float* hb = in_s + kb * BPC + h * 4;
#pragma unroll
        for (int ch = 0; ch < KSL / 4; ch++) {
            float4 q0 = wq[ch * 32];          // rows 4kq+0,1 x cols 2cp,2cp+1
            float4 q1 = wq[ch * 32 + 1];      // rows 4kq+2,3
            const ulonglong2* hp = (const ulonglong2*)(hb + ch * 32);
            ulonglong2 h0 = hp[0];            // row 0: batches 4h..4h+3
            ulonglong2 h1 = hp[2];            // row 1
            ulonglong2 h2 = hp[4];            // row 2
            ulonglong2 h3 = hp[6];            // row 3
            ull w2;
            w2 = pack2(q0.x, q0.x); ffma2(A00, w2, h0.x); ffma2(A01, w2, h0.y);
            w2 = pack2(q0.y, q0.y); ffma2(A10, w2, h0.x); ffma2(A11, w2, h0.y);
            w2 = pack2(q0.z, q0.z); ffma2(A00, w2, h1.x); ffma2(A01, w2, h1.y);
            w2 = pack2(q0.w, q0.w); ffma2(A10, w2, h1.x); ffma2(A11, w2, h1.y);
            w2 = pack2(q1.x, q1.x); ffma2(A00, w2, h2.x); ffma2(A01, w2, h2.y);
            w2 = pack2(q1.y, q1.y); ffma2(A10, w2, h2.x); ffma2(A11, w2, h2.y);
            w2 = pack2(q1.z, q1.z); ffma2(A00, w2, h3.x); ffma2(A01, w2, h3.y);
            w2 = pack2(q1.w, q1.w); ffma2(A10, w2, h3.x); ffma2(A11, w2, h3.y);
        }

        // ---- red store: col 2cp at cp*8+4h, col 2cp+1 at 128+cp*8+4h ----
        {
            *(ulonglong2*)(rw + (cp << 3) + (h << 2))       = make_ulonglong2(A00, A01);
            *(ulonglong2*)(rw + 128 + (cp << 3) + (h << 2)) = make_ulonglong2(A10, A11);
        }
        __syncthreads();

        // ---- update: tid<256, uc=tid&31 (c), ub=tid>>5 (b) ----
        if (tid < 256) {
            const int ao = ((uc & 1) << 7) + ((uc >> 1) << 3) + ub;
            float pre = bi;
#pragma unroll
            for (int w = 0; w < NW; w++)
                pre += red[w * (COLS * BPC) + ao];
            float drive = tanhf(pre);
            hz_r += DT_C * (drive - gam * hy_r - epc * hz_r);
            hy_r += DT_C * hz_r;

            __stcg(&g_hyT2[p ^ 1][bg][hg * BPC + ub], hy_r);
            __threadfence();
        }
        __syncthreads();
        if (tid == 0) st_rel(&g_flags[bg][cgrp], (unsigned)(t + 1));

        // out stores off the inter-CTA critical path
        if (tid < 256) {
            const size_t obase = (size_t)(b0g + ub) * (TT * NHID) + (size_t)t * NHID + hg;
            out[obase]       = hy_r;
            out[obase + BTH] = hz_r;
        }
    }
}

// ------------------------------------------------------------------
extern "C" void kernel_launch(void* const* d_in, const int* in_sizes, int n_in,
                              void* d_out, int out_size) {
    const float* x     = (const float*)d_in[0];
    const float* x2h   = (const float*)d_in[1];
    const float* h2h   = (const float*)d_in[2];
    const float* gamma = (const float*)d_in[3];
    const float* eps   = (const float*)d_in[4];
    const float* bias  = (const float*)d_in[5];
    float* out = (float*)d_out;

    cudaFuncSetAttribute(k_recur, cudaFuncAttributeMaxDynamicSharedMemorySize, SMEM_BYTES);

    k_init<<<64, 256>>>();
    k_xpose<<<512, 256>>>(x);
    // u and spike outputs are identically zero (u never leaves 0)
    k_zero<<<2048, 256>>>(out + (size_t)2 * BTH, (2 * BTH) / 4);
    k_recur<<<NCTA, TPB, SMEM_BYTES>>>(x2h, h2h, gamma, eps, bias, out);
}

// round 10
// speedup vs baseline: 1.7603x; 1.3266x over previous
#include <cuda_runtime.h>
#include <cstdint>

// Problem constants
#define BATCH 32
#define TT 512
#define NINP 128
#define NHID 1024
#define KTOT 1152
#define DT_C 0.042f
#define EPSH 512.0f               // HARMONIC = N_HID * 0.5

// Geometry: 128 CTAs = 32 col-groups x 4 batch-groups, 512 threads (16 warps)
#define NCTA 128
#define COLS 32
#define BPC  8
#define TPB  512
#define NW   16
#define KSL  72                   // k-rows per warp

#define BTH (BATCH * TT * NHID)

// SMEM (floats)
#define OFF_W   0
#define SZ_W    (KTOT * COLS)     // 36864, packed [k/4][c/2][8]
#define OFF_IN  (OFF_W + SZ_W)
#define SZ_IN   (KTOT * BPC)      // 9216, [k][8b]
#define OFF_RED (OFF_IN + SZ_IN)
#define SZ_RED  (NW * COLS * BPC) // 4096
#define OFF_GO  (OFF_RED + SZ_RED)
#define SMEM_FLOATS (OFF_GO + 32)
#define SMEM_BYTES  (SMEM_FLOATS * 4)

// ---- device scratch ----
__device__ float g_xT2[4 * TT * NINP * BPC];   // [bg][t][i][8b]
__device__ float g_hyT2[2][4][NHID * BPC];     // [parity][bg][h][8b]
__device__ __align__(128) unsigned g_flags[4][32];  // [bg][cgrp]

typedef unsigned long long ull;

__device__ __forceinline__ void ffma2(ull& acc, ull a, ull b) {
    asm("fma.rn.f32x2 %0, %1, %2, %0;" : "+l"(acc) : "l"(a), "l"(b));
}
__device__ __forceinline__ ull pack2(float lo, float hi) {
    ull r; asm("mov.b64 %0, {%1, %2};" : "=l"(r) : "f"(lo), "f"(hi)); return r;
}
__device__ __forceinline__ unsigned ld_acq(const unsigned* p) {
    unsigned v;
    asm volatile("ld.global.acquire.gpu.u32 %0, [%1];" : "=r"(v) : "l"(p));
    return v;
}
__device__ __forceinline__ void st_rel(unsigned* p, unsigned v) {
    asm volatile("st.global.release.gpu.u32 [%0], %1;" :: "l"(p), "r"(v));
}

// ------------------------------------------------------------------
__global__ void k_init() {
    int idx = blockIdx.x * blockDim.x + threadIdx.x;
    if (idx < NCTA) (&g_flags[0][0])[idx] = 0;
    int stride = gridDim.x * blockDim.x;
    for (int i = idx; i < 4 * NHID * BPC; i += stride)
        g_hyT2[0][0][i] = 0.0f;
}

__global__ void k_zero(float* __restrict__ p, int n4) {
    int idx = blockIdx.x * blockDim.x + threadIdx.x;
    int stride = gridDim.x * blockDim.x;
    float4 z = make_float4(0.f, 0.f, 0.f, 0.f);
    float4* p4 = reinterpret_cast<float4*>(p);
    for (int i = idx; i < n4; i += stride) p4[i] = z;
}

// x[b][t][i] -> g_xT2[bg][t][i][b&7]
__global__ void k_xpose(const float* __restrict__ x) {
    int idx = blockIdx.x * blockDim.x + threadIdx.x;
    int stride = gridDim.x * blockDim.x;
    const int N = 4 * TT * NINP * BPC;
    for (int o = idx; o < N; o += stride) {
        int blo = o & 7;
        int i = (o >> 3) & (NINP - 1);
        int t = (o >> 10) & (TT - 1);
        int bg = o >> 19;
        g_xT2[o] = x[((size_t)(bg * 8 + blo) * TT + t) * NINP + i];
    }
}

// ------------------------------------------------------------------
// persistent recurrent kernel: 128 CTAs x 512 threads
// handshake: warp 0 polls all 32 producer flags with ONE coalesced load
// per round, then releases a SMEM gate; everyone else spins on SMEM.
// ------------------------------------------------------------------
__global__ void __launch_bounds__(TPB, 1) k_recur(
    const float* __restrict__ x2h,
    const float* __restrict__ h2h,
    const float* __restrict__ gamma,
    const float* __restrict__ eps,
    const float* __restrict__ bias,
    float* __restrict__ out)
{
    extern __shared__ float sm[];
    float* w_s  = sm + OFF_W;     // packed [kq][cp][r0c0,r0c1,...,r3c0,r3c1]
    float* in_s = sm + OFF_IN;    // [k][8b]
    float* red  = sm + OFF_RED;   // [w][256]
    volatile unsigned* go = (volatile unsigned*)(sm + OFF_GO);

    const int tid  = threadIdx.x;
    const int wid  = tid >> 5;
    const int lane = tid & 31;
    const int cp   = lane >> 1;   // 0..15
    const int h    = lane & 1;    // 0..1
    const int cgrp = blockIdx.x >> 2;
    const int bg   = blockIdx.x & 3;
    const int cg0  = cgrp * COLS;
    const int b0g  = bg * BPC;
    const int kb   = wid * KSL;

    // --- weights: coalesced global read -> packed SMEM ---
    for (int idx = tid; idx < KTOT * COLS; idx += TPB) {
        int k = idx >> 5;
        int c = idx & 31;
        float v = (k < NINP) ? x2h[(size_t)k * NHID + cg0 + c]
                             : h2h[(size_t)(k - NINP) * NHID + cg0 + c];
        w_s[((k >> 2) << 7) + ((c >> 1) << 3) + ((k & 3) << 1) + (c & 1)] = v;
    }
    if (tid == 0) *go = 0;

    // --- update params (tid<256: uc=tid&31, ub=tid>>5) ---
    const int uc = tid & 31;
    const int ub = (tid >> 5) & 7;
    const int hg = cg0 + uc;
    float hy_r = 0.f, hz_r = 0.f;
    float gam = 0.f, epc = 0.f, bi = 0.f;
    if (tid < 256) {
        gam = gamma[hg];
        epc = eps[hg] * EPSH;
        bi  = bias[hg];
    }

    const float4* xs_all = (const float4*)(g_xT2 + (size_t)bg * (TT * NINP * BPC));
    const float4* wq = (const float4*)w_s + ((kb >> 2) << 5) + (cp << 1);
    float4* dst4 = (float4*)in_s;
    float* rw = red + wid * (COLS * BPC);
    const unsigned* flg = &g_flags[bg][0];

    __syncthreads();

    for (int t = 0; t < TT; t++) {
        const int p = t & 1;

        // ---- gate: warp 0 polls all 32 flags (1 coalesced load/round) ----
        if (wid == 0) {
            const unsigned want = (unsigned)t;
            while (ld_acq(flg + lane) < want) { }
            __syncwarp();
            if (lane == 0) {
                __threadfence_block();
                *go = (unsigned)(t + 1);
            }
        }
        // all warps (incl. warp 0) wait on the SMEM gate
        while (*go < (unsigned)(t + 1)) { }
        __threadfence_block();

        // ---- stage own 72 rows (144 float4): x via L1, hy via L2 ----
        {
            const float4* xs = xs_all + (size_t)t * (NINP * BPC / 4);
            const float4* hy4 = (const float4*)(&g_hyT2[p][bg][0]);
#pragma unroll
            for (int i = lane; i < KSL * 2; i += 32) {
                int f4 = kb * 2 + i;
                float4 v = (f4 < NINP * 2) ? __ldg(xs + f4)
                                           : __ldcg(hy4 + (f4 - NINP * 2));
                dst4[f4] = v;
            }
        }
        __syncwarp();

        // ---- GEMM: 18 chunks x (4 k-rows, 2 cols/lane, 4 batches/lane) ----
        ull A00 = 0, A01 = 0, A10 = 0, A11 = 0;
        const float* hb = in_s + kb * BPC + h * 4;
#pragma unroll
        for (int ch = 0; ch < KSL / 4; ch++) {
            float4 q0 = wq[ch * 32];
            float4 q1 = wq[ch * 32 + 1];
            const ulonglong2* hp = (const ulonglong2*)(hb + ch * 32);
            ulonglong2 h0 = hp[0];
            ulonglong2 h1 = hp[2];
            ulonglong2 h2 = hp[4];
            ulonglong2 h3 = hp[6];
            ull w2;
            w2 = pack2(q0.x, q0.x); ffma2(A00, w2, h0.x); ffma2(A01, w2, h0.y);
            w2 = pack2(q0.y, q0.y); ffma2(A10, w2, h0.x); ffma2(A11, w2, h0.y);
            w2 = pack2(q0.z, q0.z); ffma2(A00, w2, h1.x); ffma2(A01, w2, h1.y);
            w2 = pack2(q0.w, q0.w); ffma2(A10, w2, h1.x); ffma2(A11, w2, h1.y);
            w2 = pack2(q1.x, q1.x); ffma2(A00, w2, h2.x); ffma2(A01, w2, h2.y);
            w2 = pack2(q1.y, q1.y); ffma2(A10, w2, h2.x); ffma2(A11, w2, h2.y);
            w2 = pack2(q1.z, q1.z); ffma2(A00, w2, h3.x); ffma2(A01, w2, h3.y);
            w2 = pack2(q1.w, q1.w); ffma2(A10, w2, h3.x); ffma2(A11, w2, h3.y);
        }

        // ---- red store: col 2cp at cp*8+4h, col 2cp+1 at 128+cp*8+4h ----
        {
            *(ulonglong2*)(rw + (cp << 3) + (h << 2))       = make_ulonglong2(A00, A01);
            *(ulonglong2*)(rw + 128 + (cp << 3) + (h << 2)) = make_ulonglong2(A10, A11);
        }
        __syncthreads();

        // ---- update: tid<256, uc=tid&31 (c), ub=tid>>5 (b) ----
        if (tid < 256) {
            const int ao = ((uc & 1) << 7) + ((uc >> 1) << 3) + ub;
            float pre = bi;
#pragma unroll
            for (int w = 0; w < NW; w++)
                pre += red[w * (COLS * BPC) + ao];
            float drive = tanhf(pre);
            hz_r += DT_C * (drive - gam * hy_r - epc * hz_r);
            hy_r += DT_C * hz_r;

            __stcg(&g_hyT2[p ^ 1][bg][hg * BPC + ub], hy_r);
        }
        __syncthreads();

        // ---- single-fence release (cooperative-groups pattern) ----
        if (tid == 0) {
            __threadfence();
            st_rel(&g_flags[bg][cgrp], (unsigned)(t + 1));
        }

        // out stores off the inter-CTA critical path
        if (tid < 256) {
            const size_t obase = (size_t)(b0g + ub) * (TT * NHID) + (size_t)t * NHID + hg;
            out[obase]       = hy_r;
            out[obase + BTH] = hz_r;
        }
    }
}

// ------------------------------------------------------------------
extern "C" void kernel_launch(void* const* d_in, const int* in_sizes, int n_in,
                              void* d_out, int out_size) {
    const float* x     = (const float*)d_in[0];
    const float* x2h   = (const float*)d_in[1];
    const float* h2h   = (const float*)d_in[2];
    const float* gamma = (const float*)d_in[3];
    const float* eps   = (const float*)d_in[4];
    const float* bias  = (const float*)d_in[5];
    float* out = (float*)d_out;

    cudaFuncSetAttribute(k_recur, cudaFuncAttributeMaxDynamicSharedMemorySize, SMEM_BYTES);

    k_init<<<64, 256>>>();
    k_xpose<<<512, 256>>>(x);
    // u and spike outputs are identically zero (u never leaves 0)
    k_zero<<<2048, 256>>>(out + (size_t)2 * BTH, (2 * BTH) / 4);
    k_recur<<<NCTA, TPB, SMEM_BYTES>>>(x2h, h2h, gamma, eps, bias, out);
}

// round 11
// speedup vs baseline: 2.0451x; 1.1618x over previous
#include <cuda_runtime.h>
#include <cstdint>

// Problem constants
#define BATCH 32
#define TT 512
#define NINP 128
#define NHID 1024
#define KTOT 1152
#define DT_C 0.042f
#define EPSH 512.0f               // HARMONIC = N_HID * 0.5

// Geometry: 128 CTAs = 32 col-groups x 4 batch-groups, 512 threads (16 warps)
#define NCTA 128
#define COLS 32
#define BPC  8
#define TPB  512
#define NW   16
#define KSL  72                   // k-rows per warp

#define BTH (BATCH * TT * NHID)

// SMEM (floats)
#define OFF_W   0
#define SZ_W    (KTOT * COLS)     // 36864, packed [k/4][c/2][8]
#define OFF_IN  (OFF_W + SZ_W)
#define SZ_IN   (KTOT * BPC)      // 9216, [k][8b]
#define OFF_RED (OFF_IN + SZ_IN)
#define SZ_RED  (NW * COLS * BPC) // 4096
#define SMEM_FLOATS (OFF_RED + SZ_RED)
#define SMEM_BYTES  (SMEM_FLOATS * 4)

// ---- device scratch ----
__device__ float g_xT2[4 * TT * NINP * BPC];   // [bg][t][i][8b]
__device__ float g_hyT2[2][4][NHID * BPC];     // [parity][bg][h][8b]
// one 128B line per flag: no producer/producer or producer/poller false sharing
__device__ __align__(128) unsigned g_flags[4][32][32];

typedef unsigned long long ull;

__device__ __forceinline__ void ffma2(ull& acc, ull a, ull b) {
    asm("fma.rn.f32x2 %0, %1, %2, %0;" : "+l"(acc) : "l"(a), "l"(b));
}
__device__ __forceinline__ ull pack2(float lo, float hi) {
    ull r; asm("mov.b64 %0, {%1, %2};" : "=l"(r) : "f"(lo), "f"(hi)); return r;
}
__device__ __forceinline__ unsigned ld_acq(const unsigned* p) {
    unsigned v;
    asm volatile("ld.global.acquire.gpu.u32 %0, [%1];" : "=r"(v) : "l"(p));
    return v;
}
__device__ __forceinline__ void st_rel(unsigned* p, unsigned v) {
    asm volatile("st.global.release.gpu.u32 [%0], %1;" :: "l"(p), "r"(v));
}

// ------------------------------------------------------------------
__global__ void k_init() {
    int idx = blockIdx.x * blockDim.x + threadIdx.x;
    int stride = gridDim.x * blockDim.x;
    for (int i = idx; i < 4 * 32 * 32; i += stride)
        (&g_flags[0][0][0])[i] = 0;
    for (int i = idx; i < 4 * NHID * BPC; i += stride)
        g_hyT2[0][0][i] = 0.0f;
}

__global__ void k_zero(float* __restrict__ p, int n4) {
    int idx = blockIdx.x * blockDim.x + threadIdx.x;
    int stride = gridDim.x * blockDim.x;
    float4 z = make_float4(0.f, 0.f, 0.f, 0.f);
    float4* p4 = reinterpret_cast<float4*>(p);
    for (int i = idx; i < n4; i += stride) p4[i] = z;
}

// x[b][t][i] -> g_xT2[bg][t][i][b&7]
__global__ void k_xpose(const float* __restrict__ x) {
    int idx = blockIdx.x * blockDim.x + threadIdx.x;
    int stride = gridDim.x * blockDim.x;
    const int N = 4 * TT * NINP * BPC;
    for (int o = idx; o < N; o += stride) {
        int blo = o & 7;
        int i = (o >> 3) & (NINP - 1);
        int t = (o >> 10) & (TT - 1);
        int bg = o >> 19;
        g_xT2[o] = x[((size_t)(bg * 8 + blo) * TT + t) * NINP + i];
    }
}

// ------------------------------------------------------------------
// persistent recurrent kernel: 128 CTAs x 512 threads
// gate: warp 0 polls 32 padded flags (one line each), CTA waits at bar.sync
// ------------------------------------------------------------------
__global__ void __launch_bounds__(TPB, 1) k_recur(
    const float* __restrict__ x2h,
    const float* __restrict__ h2h,
    const float* __restrict__ gamma,
    const float* __restrict__ eps,
    const float* __restrict__ bias,
    float* __restrict__ out)
{
    extern __shared__ float sm[];
    float* w_s  = sm + OFF_W;     // packed [kq][cp][r0c0,r0c1,...,r3c0,r3c1]
    float* in_s = sm + OFF_IN;    // [k][8b]
    float* red  = sm + OFF_RED;   // [w][256]

    const int tid  = threadIdx.x;
    const int wid  = tid >> 5;
    const int lane = tid & 31;
    const int cp   = lane >> 1;   // 0..15
    const int h    = lane & 1;    // 0..1
    const int cgrp = blockIdx.x >> 2;
    const int bg   = blockIdx.x & 3;
    const int cg0  = cgrp * COLS;
    const int b0g  = bg * BPC;
    const int kb   = wid * KSL;

    // --- weights: coalesced global read -> packed SMEM ---
    for (int idx = tid; idx < KTOT * COLS; idx += TPB) {
        int k = idx >> 5;
        int c = idx & 31;
        float v = (k < NINP) ? x2h[(size_t)k * NHID + cg0 + c]
                             : h2h[(size_t)(k - NINP) * NHID + cg0 + c];
        w_s[((k >> 2) << 7) + ((c >> 1) << 3) + ((k & 3) << 1) + (c & 1)] = v;
    }

    // --- update params (tid<256: uc=tid&31, ub=tid>>5) ---
    const int uc = tid & 31;
    const int ub = (tid >> 5) & 7;
    const int hg = cg0 + uc;
    float hy_r = 0.f, hz_r = 0.f;
    float gam = 0.f, epc = 0.f, bi = 0.f;
    if (tid < 256) {
        gam = gamma[hg];
        epc = eps[hg] * EPSH;
        bi  = bias[hg];
    }

    const float4* xs_all = (const float4*)(g_xT2 + (size_t)bg * (TT * NINP * BPC));
    const float4* wq = (const float4*)w_s + ((kb >> 2) << 5) + (cp << 1);
    float4* dst4 = (float4*)in_s;
    float* rw = red + wid * (COLS * BPC);
    const unsigned* myflag = &g_flags[bg][lane][0];   // warp 0 poll target

    __syncthreads();

    for (int t = 0; t < TT; t++) {
        const int p = t & 1;

        // ---- stage x rows (no cross-CTA dependency; in_s is warp-private) ----
        {
            const float4* xs = xs_all + (size_t)t * (NINP * BPC / 4);
#pragma unroll
            for (int i = lane; i < KSL * 2; i += 32) {
                int f4 = kb * 2 + i;
                if (f4 < NINP * 2) dst4[f4] = __ldg(xs + f4);
            }
        }

        // ---- gate: warp 0 polls (one line per flag), CTA sleeps at barrier ----
        if (wid == 0) {
            const unsigned want = (unsigned)t;
            while (ld_acq(myflag) < want) { }
        }
        __syncthreads();

        // ---- stage hy rows (L2, cross-CTA coherent) ----
        {
            const float4* hy4 = (const float4*)(&g_hyT2[p][bg][0]);
#pragma unroll
            for (int i = lane; i < KSL * 2; i += 32) {
                int f4 = kb * 2 + i;
                if (f4 >= NINP * 2) dst4[f4] = __ldcg(hy4 + (f4 - NINP * 2));
            }
        }
        __syncwarp();

        // ---- GEMM: 18 chunks x (4 k-rows, 2 cols/lane, 4 batches/lane) ----
        ull A00 = 0, A01 = 0, A10 = 0, A11 = 0;
        const float* hb = in_s + kb * BPC + h * 4;
#pragma unroll
        for (int ch = 0; ch < KSL / 4; ch++) {
            float4 q0 = wq[ch * 32];
            float4 q1 = wq[ch * 32 + 1];
            const ulonglong2* hp = (const ulonglong2*)(hb + ch * 32);
            ulonglong2 h0 = hp[0];
            ulonglong2 h1 = hp[2];
            ulonglong2 h2 = hp[4];
            ulonglong2 h3 = hp[6];
            ull w2;
            w2 = pack2(q0.x, q0.x); ffma2(A00, w2, h0.x); ffma2(A01, w2, h0.y);
            w2 = pack2(q0.y, q0.y); ffma2(A10, w2, h0.x); ffma2(A11, w2, h0.y);
            w2 = pack2(q0.z, q0.z); ffma2(A00, w2, h1.x); ffma2(A01, w2, h1.y);
            w2 = pack2(q0.w, q0.w); ffma2(A10, w2, h1.x); ffma2(A11, w2, h1.y);
            w2 = pack2(q1.x, q1.x); ffma2(A00, w2, h2.x); ffma2(A01, w2, h2.y);
            w2 = pack2(q1.y, q1.y); ffma2(A10, w2, h2.x); ffma2(A11, w2, h2.y);
            w2 = pack2(q1.z, q1.z); ffma2(A00, w2, h3.x); ffma2(A01, w2, h3.y);
            w2 = pack2(q1.w, q1.w); ffma2(A10, w2, h3.x); ffma2(A11, w2, h3.y);
        }

        // ---- red store: col 2cp at cp*8+4h, col 2cp+1 at 128+cp*8+4h ----
        {
            *(ulonglong2*)(rw + (cp << 3) + (h << 2))       = make_ulonglong2(A00, A01);
            *(ulonglong2*)(rw + 128 + (cp << 3) + (h << 2)) = make_ulonglong2(A10, A11);
        }
        __syncthreads();

        // ---- update: tid<256, uc=tid&31 (c), ub=tid>>5 (b) ----
        if (tid < 256) {
            const int ao = ((uc & 1) << 7) + ((uc >> 1) << 3) + ub;
            float pre = bi;
#pragma unroll
            for (int w = 0; w < NW; w++)
                pre += red[w * (COLS * BPC) + ao];
            float drive = tanhf(pre);
            hz_r += DT_C * (drive - gam * hy_r - epc * hz_r);
            hy_r += DT_C * hz_r;

            __stcg(&g_hyT2[p ^ 1][bg][hg * BPC + ub], hy_r);
        }
        __syncthreads();

        // ---- single-fence release to this CTA's private flag line ----
        if (tid == 0) {
            __threadfence();
            st_rel(&g_flags[bg][cgrp][0], (unsigned)(t + 1));
        }

        // out stores off the inter-CTA critical path
        if (tid < 256) {
            const size_t obase = (size_t)(b0g + ub) * (TT * NHID) + (size_t)t * NHID + hg;
            out[obase]       = hy_r;
            out[obase + BTH] = hz_r;
        }
    }
}

// ------------------------------------------------------------------
extern "C" void kernel_launch(void* const* d_in, const int* in_sizes, int n_in,
                              void* d_out, int out_size) {
    const float* x     = (const float*)d_in[0];
    const float* x2h   = (const float*)d_in[1];
    const float* h2h   = (const float*)d_in[2];
    const float* gamma = (const float*)d_in[3];
    const float* eps   = (const float*)d_in[4];
    const float* bias  = (const float*)d_in[5];
    float* out = (float*)d_out;

    cudaFuncSetAttribute(k_recur, cudaFuncAttributeMaxDynamicSharedMemorySize, SMEM_BYTES);

    k_init<<<64, 256>>>();
    k_xpose<<<512, 256>>>(x);
    // u and spike outputs are identically zero (u never leaves 0)
    k_zero<<<2048, 256>>>(out + (size_t)2 * BTH, (2 * BTH) / 4);
    k_recur<<<NCTA, TPB, SMEM_BYTES>>>(x2h, h2h, gamma, eps, bias, out);
}

// round 12
// speedup vs baseline: 2.0836x; 1.0188x over previous
#include <cuda_runtime.h>
#include <cstdint>

// Problem constants
#define BATCH 32
#define TT 512
#define NINP 128
#define NHID 1024
#define KTOT 1152
#define DT_C 0.042f
#define EPSH 512.0f               // HARMONIC = N_HID * 0.5

// Geometry: 128 CTAs = 32 col-groups x 4 batch-groups, 512 threads (16 warps)
#define NCTA 128
#define COLS 32
#define BPC  8
#define TPB  512
#define NW   16
#define KSL  72                   // k-rows per warp

#define BTH (BATCH * TT * NHID)

// SMEM (floats)
#define OFF_W   0
#define SZ_W    (KTOT * COLS)     // 36864, packed [k/4][c/2][8]
#define OFF_IN  (OFF_W + SZ_W)
#define SZ_IN   (KTOT * BPC)      // 9216, [k][8b]
#define OFF_RED (OFF_IN + SZ_IN)
#define SZ_RED  (NW * COLS * BPC) // 4096
#define SMEM_FLOATS (OFF_RED + SZ_RED)
#define SMEM_BYTES  (SMEM_FLOATS * 4)

// ---- device scratch ----
__device__ float g_xT2[4 * TT * NINP * BPC];   // [bg][t][i][8b]
__device__ float g_hyT2[2][4][NHID * BPC];     // [parity][bg][h][8b]
// one 128B line per flag: no false sharing between producers or pollers
__device__ __align__(128) unsigned g_flags[4][32][32];

typedef unsigned long long ull;

__device__ __forceinline__ void ffma2(ull& acc, ull a, ull b) {
    asm("fma.rn.f32x2 %0, %1, %2, %0;" : "+l"(acc) : "l"(a), "l"(b));
}
__device__ __forceinline__ ull pack2(float lo, float hi) {
    ull r; asm("mov.b64 %0, {%1, %2};" : "=l"(r) : "f"(lo), "f"(hi)); return r;
}
__device__ __forceinline__ unsigned ld_acq(const unsigned* p) {
    unsigned v;
    asm volatile("ld.global.acquire.gpu.u32 %0, [%1];" : "=r"(v) : "l"(p));
    return v;
}
__device__ __forceinline__ void st_rel(unsigned* p, unsigned v) {
    asm volatile("st.global.release.gpu.u32 [%0], %1;" :: "l"(p), "r"(v));
}

// ------------------------------------------------------------------
__global__ void k_init() {
    int idx = blockIdx.x * blockDim.x + threadIdx.x;
    int stride = gridDim.x * blockDim.x;
    for (int i = idx; i < 4 * 32 * 32; i += stride)
        (&g_flags[0][0][0])[i] = 0;
    for (int i = idx; i < 4 * NHID * BPC; i += stride)
        g_hyT2[0][0][i] = 0.0f;
}

__global__ void k_zero(float* __restrict__ p, int n4) {
    int idx = blockIdx.x * blockDim.x + threadIdx.x;
    int stride = gridDim.x * blockDim.x;
    float4 z = make_float4(0.f, 0.f, 0.f, 0.f);
    float4* p4 = reinterpret_cast<float4*>(p);
    for (int i = idx; i < n4; i += stride) p4[i] = z;
}

// x[b][t][i] -> g_xT2[bg][t][i][b&7]
__global__ void k_xpose(const float* __restrict__ x) {
    int idx = blockIdx.x * blockDim.x + threadIdx.x;
    int stride = gridDim.x * blockDim.x;
    const int N = 4 * TT * NINP * BPC;
    for (int o = idx; o < N; o += stride) {
        int blo = o & 7;
        int i = (o >> 3) & (NINP - 1);
        int t = (o >> 10) & (TT - 1);
        int bg = o >> 19;
        g_xT2[o] = x[((size_t)(bg * 8 + blo) * TT + t) * NINP + i];
    }
}

// ------------------------------------------------------------------
// persistent recurrent kernel: 128 CTAs x 512 threads
// fine-grained deps: each warp polls only the <=4 producer flags covering
// its own 72 hy rows (padded lines), then runs its GEMM immediately.
// ------------------------------------------------------------------
__global__ void __launch_bounds__(TPB, 1) k_recur(
    const float* __restrict__ x2h,
    const float* __restrict__ h2h,
    const float* __restrict__ gamma,
    const float* __restrict__ eps,
    const float* __restrict__ bias,
    float* __restrict__ out)
{
    extern __shared__ float sm[];
    float* w_s  = sm + OFF_W;     // packed [kq][cp][r0c0,r0c1,...,r3c0,r3c1]
    float* in_s = sm + OFF_IN;    // [k][8b]
    float* red  = sm + OFF_RED;   // [w][256]

    const int tid  = threadIdx.x;
    const int wid  = tid >> 5;
    const int lane = tid & 31;
    const int cp   = lane >> 1;   // 0..15
    const int h    = lane & 1;    // 0..1
    const int cgrp = blockIdx.x >> 2;
    const int bg   = blockIdx.x & 3;
    const int cg0  = cgrp * COLS;
    const int b0g  = bg * BPC;
    const int kb   = wid * KSL;

    // --- weights: coalesced global read -> packed SMEM ---
    for (int idx = tid; idx < KTOT * COLS; idx += TPB) {
        int k = idx >> 5;
        int c = idx & 31;
        float v = (k < NINP) ? x2h[(size_t)k * NHID + cg0 + c]
                             : h2h[(size_t)(k - NINP) * NHID + cg0 + c];
        w_s[((k >> 2) << 7) + ((c >> 1) << 3) + ((k & 3) << 1) + (c & 1)] = v;
    }

    // --- update params (tid<256: uc=tid&31, ub=tid>>5) ---
    const int uc = tid & 31;
    const int ub = (tid >> 5) & 7;
    const int hg = cg0 + uc;
    float hy_r = 0.f, hz_r = 0.f;
    float gam = 0.f, epc = 0.f, bi = 0.f;
    if (tid < 256) {
        gam = gamma[hg];
        epc = eps[hg] * EPSH;
        bi  = bias[hg];
    }

    // --- this warp's producer flags (hy rows [kb-128, kb+72-128)) ---
    int p0 = 0, npf = 0;
    {
        int ke = kb + KSL;
        if (ke > NINP) {
            int h0 = ((kb > NINP) ? kb : NINP) - NINP;
            int h1 = ke - NINP - 1;
            p0 = h0 >> 5;
            npf = (h1 >> 5) - p0 + 1;   // <= 4
        }
    }
    const unsigned* myflag = &g_flags[bg][p0 + lane][0];  // lanes 0..npf-1 poll

    const float4* xs_all = (const float4*)(g_xT2 + (size_t)bg * (TT * NINP * BPC));
    const float4* wq = (const float4*)w_s + ((kb >> 2) << 5) + (cp << 1);
    float4* dst4 = (float4*)in_s;
    float* rw = red + wid * (COLS * BPC);

    __syncthreads();

    for (int t = 0; t < TT; t++) {
        const int p = t & 1;

        // ---- stage x rows (no cross-CTA dependency; in_s is warp-private) ----
        {
            const float4* xs = xs_all + (size_t)t * (NINP * BPC / 4);
#pragma unroll
            for (int i = lane; i < KSL * 2; i += 32) {
                int f4 = kb * 2 + i;
                if (f4 < NINP * 2) dst4[f4] = __ldg(xs + f4);
            }
        }

        // ---- fine-grained poll: only this warp's <=4 producers ----
        if (lane < npf) {
            const unsigned want = (unsigned)t;
            while (ld_acq(myflag) < want) { }
        }
        __syncwarp();

        // ---- stage hy rows (L2, cross-CTA coherent) ----
        {
            const float4* hy4 = (const float4*)(&g_hyT2[p][bg][0]);
#pragma unroll
            for (int i = lane; i < KSL * 2; i += 32) {
                int f4 = kb * 2 + i;
                if (f4 >= NINP * 2) dst4[f4] = __ldcg(hy4 + (f4 - NINP * 2));
            }
        }
        __syncwarp();

        // ---- GEMM: 18 chunks x (4 k-rows, 2 cols/lane, 4 batches/lane) ----
        ull A00 = 0, A01 = 0, A10 = 0, A11 = 0;
        const float* hb = in_s + kb * BPC + h * 4;
#pragma unroll
        for (int ch = 0; ch < KSL / 4; ch++) {
            float4 q0 = wq[ch * 32];
            float4 q1 = wq[ch * 32 + 1];
            const ulonglong2* hp = (const ulonglong2*)(hb + ch * 32);
            ulonglong2 h0 = hp[0];
            ulonglong2 h1 = hp[2];
            ulonglong2 h2 = hp[4];
            ulonglong2 h3 = hp[6];
            ull w2;
            w2 = pack2(q0.x, q0.x); ffma2(A00, w2, h0.x); ffma2(A01, w2, h0.y);
            w2 = pack2(q0.y, q0.y); ffma2(A10, w2, h0.x); ffma2(A11, w2, h0.y);
            w2 = pack2(q0.z, q0.z); ffma2(A00, w2, h1.x); ffma2(A01, w2, h1.y);
            w2 = pack2(q0.w, q0.w); ffma2(A10, w2, h1.x); ffma2(A11, w2, h1.y);
            w2 = pack2(q1.x, q1.x); ffma2(A00, w2, h2.x); ffma2(A01, w2, h2.y);
            w2 = pack2(q1.y, q1.y); ffma2(A10, w2, h2.x); ffma2(A11, w2, h2.y);
            w2 = pack2(q1.z, q1.z); ffma2(A00, w2, h3.x); ffma2(A01, w2, h3.y);
            w2 = pack2(q1.w, q1.w); ffma2(A10, w2, h3.x); ffma2(A11, w2, h3.y);
        }

        // ---- red store: col 2cp at cp*8+4h, col 2cp+1 at 128+cp*8+4h ----
        {
            *(ulonglong2*)(rw + (cp << 3) + (h << 2))       = make_ulonglong2(A00, A01);
            *(ulonglong2*)(rw + 128 + (cp << 3) + (h << 2)) = make_ulonglong2(A10, A11);
        }
        __syncthreads();   // by here the CTA has observed ALL 32 flags >= t

        // ---- update: tid<256, uc=tid&31 (c), ub=tid>>5 (b) ----
        if (tid < 256) {
            const int ao = ((uc & 1) << 7) + ((uc >> 1) << 3) + ub;
            float pre = bi;
#pragma unroll
            for (int w = 0; w < NW; w++)
                pre += red[w * (COLS * BPC) + ao];
            float drive = tanhf(pre);
            hz_r += DT_C * (drive - gam * hy_r - epc * hz_r);
            hy_r += DT_C * hz_r;

            __stcg(&g_hyT2[p ^ 1][bg][hg * BPC + ub], hy_r);
        }
        __syncthreads();

        // ---- single-fence release to this CTA's private flag line ----
        if (tid == 0) {
            __threadfence();
            st_rel(&g_flags[bg][cgrp][0], (unsigned)(t + 1));
        }

        // out stores off the inter-CTA critical path
        if (tid < 256) {
            const size_t obase = (size_t)(b0g + ub) * (TT * NHID) + (size_t)t * NHID + hg;
            out[obase]       = hy_r;
            out[obase + BTH] = hz_r;
        }
    }
}

// ------------------------------------------------------------------
extern "C" void kernel_launch(void* const* d_in, const int* in_sizes, int n_in,
                              void* d_out, int out_size) {
    const float* x     = (const float*)d_in[0];
    const float* x2h   = (const float*)d_in[1];
    const float* h2h   = (const float*)d_in[2];
    const float* gamma = (const float*)d_in[3];
    const float* eps   = (const float*)d_in[4];
    const float* bias  = (const float*)d_in[5];
    float* out = (float*)d_out;

    cudaFuncSetAttribute(k_recur, cudaFuncAttributeMaxDynamicSharedMemorySize, SMEM_BYTES);

    k_init<<<64, 256>>>();
    k_xpose<<<512, 256>>>(x);
    // u and spike outputs are identically zero (u never leaves 0)
    k_zero<<<2048, 256>>>(out + (size_t)2 * BTH, (2 * BTH) / 4);
    k_recur<<<NCTA, TPB, SMEM_BYTES>>>(x2h, h2h, gamma, eps, bias, out);
}